// round 14
// baseline (speedup 1.0000x reference)
#include <cuda_runtime.h>
#include <cuda_fp16.h>
#include <cstdint>

#define Bv 4
#define Tv 512
#define Iv 128
#define Hv 128
#define Gv 512   // 4*H

// ---------------- device scratch (no allocations allowed) ----------------
__device__ __align__(16) float d_WihTs[Iv * Gv];        // [K=128][512]
__device__ __align__(16) float d_WihTt[(Iv + Hv) * Gv]; // [K=256][512]
__device__ __align__(16) uint4 d_Wfs[32 * 8 * 32];      // mma A-frags (unit-major perm)
__device__ __align__(16) uint4 d_Wft[32 * 8 * 32];
__device__ __align__(16) float d_xg_s[Tv * Bv * Gv];    // [t][b][512] gate-major
__device__ __align__(16) float d_xg_t[Tv * Bv * Gv];    // [t][b][512]
__device__ __align__(16) float d_Hsh[Bv * Tv * Hv];     // [b][t][h]
__device__ __align__(16) float d_hpt[Bv * Tv * Hv];     // [b][t][n]
__device__ __align__(16) float d_ca [Bv * Tv * Hv];     // [b][s][n]
__device__ __align__(16) float d_sc [Bv * Tv * Tv];     // [b][t][s] raw scores
__device__ __align__(16) float d_R  [Bv * Tv * Hv];     // [b][t][h]

// ---------------- math helpers ----------------
__device__ __forceinline__ float ftanh_fast(float x) {
    float y;
    asm("tanh.approx.f32 %0, %1;" : "=f"(y) : "f"(x));
    return y;
}
__device__ __forceinline__ float fsig_fast(float x) {
    return fmaf(ftanh_fast(0.5f * x), 0.5f, 0.5f);
}
__device__ __forceinline__ uint32_t pack_h2(float a, float b) {
    __half2 h = __floats2half2_rn(a, b);
    return *reinterpret_cast<uint32_t*>(&h);
}
__device__ __forceinline__ void mma16816(float& d0, float& d1, float& d2, float& d3,
                                         uint4 a, uint32_t b0, uint32_t b1) {
    asm volatile(
        "mma.sync.aligned.m16n8k16.row.col.f32.f16.f16.f32 "
        "{%0,%1,%2,%3}, {%4,%5,%6,%7}, {%8,%9}, {%0,%1,%2,%3};"
        : "+f"(d0), "+f"(d1), "+f"(d2), "+f"(d3)
        : "r"(a.x), "r"(a.y), "r"(a.z), "r"(a.w), "r"(b0), "r"(b1));
}
// permuted row m' = 4*unit + gate  ->  original row = gate*128 + unit
__device__ __forceinline__ int orig_row(int r) { return (r & 3) * 128 + (r >> 2); }

__device__ __forceinline__ void mbar_wait_cluster(uint32_t mb, uint32_t parity) {
    asm volatile(
        "{\n\t"
        ".reg .pred P;\n\t"
        "W%=:\n\t"
        "mbarrier.try_wait.parity.acquire.cluster.shared::cta.b64 P, [%0], %1, 0x989680;\n\t"
        "@P bra D%=;\n\t"
        "bra W%=;\n\t"
        "D%=:\n\t"
        "}"
        :: "r"(mb), "r"(parity) : "memory");
}

// ---------------- fused prep: transposes + fragment packs ----------------
// blocks 0..63: transpose Wih_s; 64..191: transpose Wih_t;
// 192..223: pack Whh_s frags; 224..255: pack Whh_t frags.
// Fragment layout: entry (mt, kt, lane) at index mt*256 + kt*32 + lane,
// mt in [0,32) = permuted m-tile (16 rows), kt in [0,8) = k-chunk of 16.
__global__ __launch_bounds__(256) void k_prep(
    const float* __restrict__ Wih_s, const float* __restrict__ Wih_t,
    const float* __restrict__ Whh_s, const float* __restrict__ Whh_t) {
    int blk = blockIdx.x;
    int tid = threadIdx.x;
    if (blk < 192) {
        __shared__ float tile[32][33];
        const float* src;
        float* dst;
        int bx, by, K;
        if (blk < 64) { src = Wih_s; dst = d_WihTs; K = 128; bx = blk & 3;  by = blk >> 2; }
        else { int i = blk - 64; src = Wih_t; dst = d_WihTt; K = 256; bx = i & 7; by = i >> 3; }
        int tx = tid & 31, ty = tid >> 5;  // (32, 8)
        int n0 = by * 32, k0 = bx * 32;
        #pragma unroll
        for (int i = ty; i < 32; i += 8)
            tile[i][tx] = src[(n0 + i) * K + (k0 + tx)];
        __syncthreads();
        #pragma unroll
        for (int i = ty; i < 32; i += 8)
            dst[(k0 + i) * Gv + (n0 + tx)] = tile[tx][i];
    } else {
        const float* W = (blk < 224) ? Whh_s : Whh_t;
        uint4* dst = (blk < 224) ? d_Wfs : d_Wft;
        int e = ((blk < 224) ? (blk - 192) : (blk - 224)) * 256 + tid;  // 0..8191
        int mt = e >> 8, rem = e & 255;
        int kt = rem >> 5, lane = rem & 31;
        int m0 = mt * 16, k0 = kt * 16;
        int g = lane >> 2, tg = lane & 3;
        const float* Wm0 = W + orig_row(m0 + g) * 128;
        const float* Wm8 = W + orig_row(m0 + g + 8) * 128;
        uint4 o;
        o.x = pack_h2(Wm0[k0 + 2 * tg],     Wm0[k0 + 2 * tg + 1]);
        o.y = pack_h2(Wm8[k0 + 2 * tg],     Wm8[k0 + 2 * tg + 1]);
        o.z = pack_h2(Wm0[k0 + 2 * tg + 8], Wm0[k0 + 2 * tg + 9]);
        o.w = pack_h2(Wm8[k0 + 2 * tg + 8], Wm8[k0 + 2 * tg + 9]);
        dst[e] = o;
    }
}

// ---------------- input-gate projection (4 timesteps / block) ------------
__global__ __launch_bounds__(512) void k_proj_gates(
    const float* __restrict__ A1, const float* __restrict__ bias, int task) {
    int b = blockIdx.y;
    int t0 = blockIdx.x * 4;
    const float* WT = task ? d_WihTt : d_WihTs;
    float* out = task ? d_xg_t : d_xg_s;
    __shared__ float sa[4][256];
    int tid = threadIdx.x;
    {
        int tt = tid >> 7, k = tid & 127;
        sa[tt][k] = A1[((b * Tv) + (t0 + tt)) * Iv + k];
        if (task) sa[tt][128 + k] = d_R[((b * Tv) + (t0 + tt)) * Hv + k];
    }
    __syncthreads();
    int n = tid;
    float bn = bias[n];
    float a0 = bn, a1 = bn, a2 = bn, a3 = bn;
    int K = task ? 256 : 128;
    #pragma unroll 4
    for (int k = 0; k < K; k++) {
        float w = WT[k * Gv + n];
        a0 = fmaf(w, sa[0][k], a0);
        a1 = fmaf(w, sa[1][k], a1);
        a2 = fmaf(w, sa[2][k], a2);
        a3 = fmaf(w, sa[3][k], a3);
    }
    out[((t0 + 0) * Bv + b) * Gv + n] = a0;
    out[((t0 + 1) * Bv + b) * Gv + n] = a1;
    out[((t0 + 2) * Bv + b) * Gv + n] = a2;
    out[((t0 + 3) * Bv + b) * Gv + n] = a3;
}

// ---------------- sequential LSTM: 2-CTA cluster, all 4 batches ----------
// CTA r owns permuted gate rows [256r, 256r+256) = units [64r, 64r+64).
// Full h (fp16) replicated per CTA, double-buffered by step parity; cell
// threads write local + peer (DSMEM) h. One mbarrier generation per step
// (512 arrivals: 256 local + 256 remote). Remote arrive carries
// RELEASE.CLUSTER so the peer's acquire-wait observes the DSMEM h store
// (this ordering was the R12 correctness bug).
#define HB_STRIDE 136   // halves per hb row
#define SG_STRIDE 6     // floats per sgb row
__global__ __cluster_dims__(2, 1, 1) __launch_bounds__(512, 1)
void k_lstm(int task, float* __restrict__ out_ext) {
    const float* __restrict__ xg = task ? d_xg_t : d_xg_s;
    const uint4* __restrict__ Wf = task ? d_Wft : d_Wfs;
    float* __restrict__ Hout = task ? out_ext : d_Hsh;

    __shared__ __align__(16) __half hb[2][8 * HB_STRIDE];  // [parity][n][k]
    __shared__ __align__(16) float sgb[256 * SG_STRIDE];   // this CTA's gate rows
    __shared__ __align__(8) uint64_t mbar;

    int tid = threadIdx.x;
    int rank = blockIdx.x;           // == cluster_ctarank for grid 2 / cluster 2
    int peer = rank ^ 1;
    int warp = tid >> 5, lane = tid & 31;
    int g = lane >> 2, tg = lane & 3;

    // A fragments: this CTA-warp's m-tile = 16*rank + warp
    uint4 af[8];
    #pragma unroll
    for (int kt = 0; kt < 8; kt++)
        af[kt] = Wf[(16 * rank + warp) * 256 + kt * 32 + lane];

    for (int j = tid; j < 8 * HB_STRIDE; j += 512) {
        hb[0][j] = __float2half(0.0f);
        hb[1][j] = __float2half(0.0f);
    }
    uint32_t mb = (uint32_t)__cvta_generic_to_shared(&mbar);
    if (tid == 0)
        asm volatile("mbarrier.init.shared.b64 [%0], %1;" :: "r"(mb), "r"(512) : "memory");
    __syncthreads();
    // cluster-wide: mbar init + hb zero visible before any remote traffic
    asm volatile("barrier.cluster.arrive.aligned;" ::: "memory");
    asm volatile("barrier.cluster.wait.aligned;" ::: "memory");

    // remote mbar address (peer's smem)
    uint32_t rmb;
    asm("mapa.shared::cluster.u32 %0, %1, %2;" : "=r"(rmb) : "r"(mb), "r"(peer));

    // cell-thread constants
    int cb = tid >> 6, cul = tid & 63;          // batch, local unit (tid < 256)
    int cu = rank * 64 + cul;                   // global unit
    float c_reg = 0.0f;

    for (int t = 0; t < Tv; t++) {
        int p = t & 1;
        // prefetch xg for this thread's cell (hidden under mma phase)
        float xgi = 0.f, xgf = 0.f, xgg = 0.f, xgo = 0.f;
        if (tid < 256) {
            const float* xr = xg + ((size_t)t * Bv + cb) * Gv + cu;
            xgi = xr[0]; xgf = xr[128]; xgg = xr[256]; xgo = xr[384];
        }

        // B fragments from current h buffer
        const __half* hbuf = hb[p];
        uint32_t bf0[8], bf1[8];
        #pragma unroll
        for (int kt = 0; kt < 8; kt++) {
            int base = g * HB_STRIDE + kt * 16 + tg * 2;
            bf0[kt] = *reinterpret_cast<const uint32_t*>(&hbuf[base]);
            bf1[kt] = *reinterpret_cast<const uint32_t*>(&hbuf[base + 8]);
        }

        // 8 mma: 1 m-tile x 8 k-chunks
        float d0[4] = {0.f, 0.f, 0.f, 0.f};
        #pragma unroll
        for (int kt = 0; kt < 8; kt++)
            mma16816(d0[0], d0[1], d0[2], d0[3], af[kt], bf0[kt], bf1[kt]);

        // stage D into sgb (local rows [16*warp, 16*warp+16); only n<4 => tg<2)
        if (tg < 2) {
            int m0 = warp * 16;
            *reinterpret_cast<float2*>(&sgb[(m0 + g)     * SG_STRIDE + tg * 2]) = make_float2(d0[0], d0[1]);
            *reinterpret_cast<float2*>(&sgb[(m0 + g + 8) * SG_STRIDE + tg * 2]) = make_float2(d0[2], d0[3]);
        }
        __syncthreads();

        // cell update: 256 threads, one (batch, unit) each
        if (tid < 256) {
            int lr = 4 * cul;
            float gi = sgb[(lr + 0) * SG_STRIDE + cb] + xgi;
            float gf = sgb[(lr + 1) * SG_STRIDE + cb] + xgf;
            float gg = sgb[(lr + 2) * SG_STRIDE + cb] + xgg;
            float go = sgb[(lr + 3) * SG_STRIDE + cb] + xgo;
            float iv = fsig_fast(gi), fv = fsig_fast(gf), ov = fsig_fast(go);
            float gt = ftanh_fast(gg);
            c_reg = fv * c_reg + iv * gt;
            float hv = ov * ftanh_fast(c_reg);

            __half hhv = __float2half(hv);
            __half* dsth = &hb[p ^ 1][cb * HB_STRIDE + cu];
            *dsth = hhv;                                        // local
            uint32_t la = (uint32_t)__cvta_generic_to_shared(dsth);
            uint32_t ra;
            asm("mapa.shared::cluster.u32 %0, %1, %2;" : "=r"(ra) : "r"(la), "r"(peer));
            unsigned short hu = __half_as_ushort(hhv);
            asm volatile("st.shared::cluster.u16 [%0], %1;" :: "r"(ra), "h"(hu) : "memory");

            Hout[((size_t)cb * Tv + t) * Hv + cu] = hv;

            // signal: local arrive (release.cta covers local hb store),
            // remote arrive with RELEASE.CLUSTER (orders the DSMEM store
            // before the arrival the peer's acquire-wait observes).
            asm volatile("mbarrier.arrive.release.cta.shared::cta.b64 _, [%0];"
                         :: "r"(mb) : "memory");
            asm volatile("mbarrier.arrive.release.cluster.shared::cluster.b64 _, [%0];"
                         :: "r"(rmb) : "memory");
        }

        // all threads wait for generation t (both CTAs' h published)
        mbar_wait_cluster(mb, (uint32_t)(t & 1));
    }

    // no CTA exits while peer stores may still target its smem
    asm volatile("barrier.cluster.arrive.aligned;" ::: "memory");
    asm volatile("barrier.cluster.wait.aligned;" ::: "memory");
}

// ---------------- attention projections (4 rows / block, grid 512) -------
__global__ __launch_bounds__(128) void k_att_proj(
    const float* __restrict__ x,
    const float* __restrict__ Wx, const float* __restrict__ Wht,
    const float* __restrict__ Whs, const float* __restrict__ bs) {
    int b = blockIdx.y;
    int t0 = blockIdx.x * 4;
    __shared__ float sx[4][Iv];
    __shared__ float shh[4][Hv];
    int tid = threadIdx.x;  // 128
    {
        int tt = tid >> 5;
        int k0 = (tid & 31) * 4;
        #pragma unroll
        for (int q = 0; q < 4; q++) {
            sx[tt][k0 + q]  = x[((b * Tv) + (t0 + tt)) * Iv + k0 + q];
            shh[tt][k0 + q] = d_Hsh[((b * Tv) + (t0 + tt)) * Hv + k0 + q];
        }
    }
    __syncthreads();
    int n = tid;
    float at[4], ac[4];
    float bsn = bs[n];
    #pragma unroll
    for (int tt = 0; tt < 4; tt++) { at[tt] = 0.f; ac[tt] = bsn; }
    #pragma unroll 4
    for (int k = 0; k < 128; k++) {
        float wt = Wht[k * Hv + n];
        float ws = Whs[k * Hv + n];
        float wx = Wx [k * Hv + n];
        #pragma unroll
        for (int tt = 0; tt < 4; tt++) {
            at[tt] = fmaf(shh[tt][k], wt, at[tt]);
            ac[tt] = fmaf(sx[tt][k], wx, fmaf(shh[tt][k], ws, ac[tt]));
        }
    }
    #pragma unroll
    for (int tt = 0; tt < 4; tt++) {
        d_hpt[((b * Tv) + (t0 + tt)) * Hv + n] = at[tt];
        d_ca [((b * Tv) + (t0 + tt)) * Hv + n] = ac[tt];
    }
}

// ---------------- attention scores (raw; softmax fused into k_R) ---------
__global__ __launch_bounds__(256) void k_scores(
    const float* __restrict__ u, const float* __restrict__ bu) {
    int b = blockIdx.z;
    int t0 = blockIdx.y * 32;
    int s0 = blockIdx.x * 32;
    __shared__ float sat[32][128];
    __shared__ float scs[32][129];
    __shared__ float su[128];
    int tid = threadIdx.y * 32 + threadIdx.x;  // 256
    for (int i = tid; i < 32 * 128; i += 256) {
        int r = i >> 7, h = i & 127;
        sat[r][h] = d_hpt[((b * Tv) + (t0 + r)) * Hv + h];
        scs[r][h] = d_ca [((b * Tv) + (s0 + r)) * Hv + h];
    }
    if (tid < 128) su[tid] = u[tid];
    __syncthreads();
    int si = threadIdx.x;       // 0..31
    int ti = threadIdx.y * 4;   // 0..28
    float a0 = 0.f, a1 = 0.f, a2 = 0.f, a3 = 0.f;
    #pragma unroll 4
    for (int h = 0; h < 128; h++) {
        float cv = scs[si][h];
        float uv = su[h];
        a0 = fmaf(uv, ftanh_fast(sat[ti + 0][h] + cv), a0);
        a1 = fmaf(uv, ftanh_fast(sat[ti + 1][h] + cv), a1);
        a2 = fmaf(uv, ftanh_fast(sat[ti + 2][h] + cv), a2);
        a3 = fmaf(uv, ftanh_fast(sat[ti + 3][h] + cv), a3);
    }
    float bub = bu[0];
    d_sc[((size_t)(b * Tv) + (t0 + ti + 0)) * Tv + s0 + si] = a0 + bub;
    d_sc[((size_t)(b * Tv) + (t0 + ti + 1)) * Tv + s0 + si] = a1 + bub;
    d_sc[((size_t)(b * Tv) + (t0 + ti + 2)) * Tv + s0 + si] = a2 + bub;
    d_sc[((size_t)(b * Tv) + (t0 + ti + 3)) * Tv + s0 + si] = a3 + bub;
}

// ---------------- fused softmax + R ----------------
__global__ __launch_bounds__(128) void k_R() {
    int b = blockIdx.y;
    int t0 = blockIdx.x * 8;
    __shared__ float sb[8][Tv];
    int tid = threadIdx.x;  // 128
    int warp = tid >> 5, lane = tid & 31;
    for (int i = tid; i < 8 * Tv; i += 128) {
        int tt = i >> 9, s = i & 511;
        sb[tt][s] = d_sc[((size_t)(b * Tv) + (t0 + tt)) * Tv + s];
    }
    __syncthreads();
    #pragma unroll
    for (int q = 0; q < 2; q++) {
        int r = 2 * warp + q;
        float m = -1e30f;
        #pragma unroll 4
        for (int s = lane; s < Tv; s += 32) m = fmaxf(m, sb[r][s]);
        #pragma unroll
        for (int off = 16; off > 0; off >>= 1)
            m = fmaxf(m, __shfl_xor_sync(0xFFFFFFFF, m, off));
        float sum = 0.f;
        #pragma unroll 4
        for (int s = lane; s < Tv; s += 32) {
            float e = __expf(sb[r][s] - m);
            sb[r][s] = e;
            sum += e;
        }
        #pragma unroll
        for (int off = 16; off > 0; off >>= 1)
            sum += __shfl_xor_sync(0xFFFFFFFF, sum, off);
        float inv = __fdividef(1.0f, sum);
        #pragma unroll 4
        for (int s = lane; s < Tv; s += 32) sb[r][s] *= inv;
    }
    __syncthreads();
    float acc[8];
    #pragma unroll
    for (int tt = 0; tt < 8; tt++) acc[tt] = 0.f;
    int h = tid;
    #pragma unroll 4
    for (int s = 0; s < Tv; s++) {
        float hv = d_Hsh[((b * Tv) + s) * Hv + h];
        #pragma unroll
        for (int tt = 0; tt < 8; tt++) acc[tt] = fmaf(sb[tt][s], hv, acc[tt]);
    }
    #pragma unroll
    for (int tt = 0; tt < 8; tt++)
        d_R[((b * Tv) + (t0 + tt)) * Hv + h] = acc[tt];
}

// ---------------- launch ----------------
extern "C" void kernel_launch(void* const* d_in, const int* in_sizes, int n_in,
                              void* d_out, int out_size) {
    const float* x       = (const float*)d_in[0];
    const float* Wih_s   = (const float*)d_in[1];
    const float* Whh_s   = (const float*)d_in[2];
    const float* b_lstms = (const float*)d_in[3];
    const float* Wx      = (const float*)d_in[4];
    const float* Wht     = (const float*)d_in[5];
    const float* Whs     = (const float*)d_in[6];
    const float* bs      = (const float*)d_in[7];
    const float* u       = (const float*)d_in[8];
    const float* bu      = (const float*)d_in[9];
    const float* Wih_t   = (const float*)d_in[10];
    const float* Whh_t   = (const float*)d_in[11];
    const float* b_lstmt = (const float*)d_in[12];
    float* out = (float*)d_out;

    k_prep<<<256, 256>>>(Wih_s, Wih_t, Whh_s, Whh_t);

    // shared LSTM (2-CTA cluster)
    k_proj_gates<<<dim3(Tv / 4, Bv), 512>>>(x, b_lstms, 0);
    k_lstm<<<2, 512>>>(0, out);

    // attention
    k_att_proj<<<dim3(Tv / 4, Bv), 128>>>(x, Wx, Wht, Whs, bs);
    k_scores<<<dim3(Tv / 32, Tv / 32, Bv), dim3(32, 8)>>>(u, bu);
    k_R<<<dim3(Tv / 8, Bv), 128>>>();

    // task LSTM (2-CTA cluster)
    k_proj_gates<<<dim3(Tv / 4, Bv), 512>>>(x, b_lstmt, 1);
    k_lstm<<<2, 512>>>(1, out);
}

// round 15
// speedup vs baseline: 1.7362x; 1.7362x over previous
#include <cuda_runtime.h>
#include <cuda_fp16.h>
#include <cstdint>

#define Bv 4
#define Tv 512
#define Iv 128
#define Hv 128
#define Gv 512   // 4*H

// ---------------- device scratch (no allocations allowed) ----------------
__device__ __align__(16) float d_WihTs[Iv * Gv];        // [K=128][512]
__device__ __align__(16) float d_WihTt[(Iv + Hv) * Gv]; // [K=256][512]
__device__ __align__(16) uint4 d_Wfs[16 * 16 * 32];     // mma A-frags (gate-major)
__device__ __align__(16) uint4 d_Wft[16 * 16 * 32];
__device__ __align__(16) float d_xg_s[Tv * Bv * Gv];    // [t][b][512]
__device__ __align__(16) float d_xg_t[Tv * Bv * Gv];    // [t][b][512]
__device__ __align__(16) float d_Hsh[Bv * Tv * Hv];     // [b][t][h]
__device__ __align__(16) float d_hpt[Bv * Tv * Hv];     // [b][t][n]
__device__ __align__(16) float d_ca [Bv * Tv * Hv];     // [b][s][n]
__device__ __align__(16) float d_sc [Bv * Tv * Tv];     // [b][t][s] raw scores
__device__ __align__(16) float d_R  [Bv * Tv * Hv];     // [b][t][h]

// ---------------- math helpers ----------------
__device__ __forceinline__ float ftanh_fast(float x) {
    float y;
    asm("tanh.approx.f32 %0, %1;" : "=f"(y) : "f"(x));
    return y;
}
__device__ __forceinline__ float fsig_fast(float x) {
    return fmaf(ftanh_fast(0.5f * x), 0.5f, 0.5f);
}
__device__ __forceinline__ uint32_t pack_h2(float a, float b) {
    __half2 h = __floats2half2_rn(a, b);
    return *reinterpret_cast<uint32_t*>(&h);
}
__device__ __forceinline__ void mma16816(float& d0, float& d1, float& d2, float& d3,
                                         uint4 a, uint32_t b0, uint32_t b1) {
    asm volatile(
        "mma.sync.aligned.m16n8k16.row.col.f32.f16.f16.f32 "
        "{%0,%1,%2,%3}, {%4,%5,%6,%7}, {%8,%9}, {%0,%1,%2,%3};"
        : "+f"(d0), "+f"(d1), "+f"(d2), "+f"(d3)
        : "r"(a.x), "r"(a.y), "r"(a.z), "r"(a.w), "r"(b0), "r"(b1));
}

// ---------------- fused prep: transposes + fragment packs ----------------
// blocks 0..63: transpose Wih_s; 64..191: transpose Wih_t;
// 192..223: pack Whh_s frags; 224..255: pack Whh_t frags. 256 threads each.
// Fragment packing uses ORIGINAL (gate-major) row order, matching k_lstm.
__global__ __launch_bounds__(256) void k_prep(
    const float* __restrict__ Wih_s, const float* __restrict__ Wih_t,
    const float* __restrict__ Whh_s, const float* __restrict__ Whh_t) {
    int blk = blockIdx.x;
    int tid = threadIdx.x;
    if (blk < 192) {
        __shared__ float tile[32][33];
        const float* src;
        float* dst;
        int bx, by, K;
        if (blk < 64) { src = Wih_s; dst = d_WihTs; K = 128; bx = blk & 3;  by = blk >> 2; }
        else { int i = blk - 64; src = Wih_t; dst = d_WihTt; K = 256; bx = i & 7; by = i >> 3; }
        int tx = tid & 31, ty = tid >> 5;  // (32, 8)
        int n0 = by * 32, k0 = bx * 32;
        #pragma unroll
        for (int i = ty; i < 32; i += 8)
            tile[i][tx] = src[(n0 + i) * K + (k0 + tx)];
        __syncthreads();
        #pragma unroll
        for (int i = ty; i < 32; i += 8)
            dst[(k0 + i) * Gv + (n0 + tx)] = tile[tx][i];
    } else {
        const float* W = (blk < 224) ? Whh_s : Whh_t;
        uint4* dst = (blk < 224) ? d_Wfs : d_Wft;
        int e = ((blk < 224) ? (blk - 192) : (blk - 224)) * 256 + tid;  // 0..8191
        int w = e >> 9, i = (e >> 5) & 15, lane = e & 31;
        int m0 = (w * 2 + (i >> 3)) * 16;
        int k0 = (i & 7) * 16;
        int g = lane >> 2, tg = lane & 3;
        const float* Wm0 = W + (m0 + g) * 128;
        const float* Wm8 = W + (m0 + g + 8) * 128;
        uint4 o;
        o.x = pack_h2(Wm0[k0 + 2 * tg],     Wm0[k0 + 2 * tg + 1]);
        o.y = pack_h2(Wm8[k0 + 2 * tg],     Wm8[k0 + 2 * tg + 1]);
        o.z = pack_h2(Wm0[k0 + 2 * tg + 8], Wm0[k0 + 2 * tg + 9]);
        o.w = pack_h2(Wm8[k0 + 2 * tg + 8], Wm8[k0 + 2 * tg + 9]);
        dst[e] = o;
    }
}

// ---------------- input-gate projection (4 timesteps / block) ------------
__global__ __launch_bounds__(512) void k_proj_gates(
    const float* __restrict__ A1, const float* __restrict__ bias, int task) {
    int b = blockIdx.y;
    int t0 = blockIdx.x * 4;
    const float* WT = task ? d_WihTt : d_WihTs;
    float* out = task ? d_xg_t : d_xg_s;
    __shared__ float sa[4][256];
    int tid = threadIdx.x;
    {
        int tt = tid >> 7, k = tid & 127;
        sa[tt][k] = A1[((b * Tv) + (t0 + tt)) * Iv + k];
        if (task) sa[tt][128 + k] = d_R[((b * Tv) + (t0 + tt)) * Hv + k];
    }
    __syncthreads();
    int n = tid;
    float bn = bias[n];
    float a0 = bn, a1 = bn, a2 = bn, a3 = bn;
    int K = task ? 256 : 128;
    #pragma unroll 4
    for (int k = 0; k < K; k++) {
        float w = WT[k * Gv + n];
        a0 = fmaf(w, sa[0][k], a0);
        a1 = fmaf(w, sa[1][k], a1);
        a2 = fmaf(w, sa[2][k], a2);
        a3 = fmaf(w, sa[3][k], a3);
    }
    out[((t0 + 0) * Bv + b) * Gv + n] = a0;
    out[((t0 + 1) * Bv + b) * Gv + n] = a1;
    out[((t0 + 2) * Bv + b) * Gv + n] = a2;
    out[((t0 + 3) * Bv + b) * Gv + n] = a3;
}

// ---------------- sequential LSTM: ONE CTA, all 4 batches (R10 version) --
// 512 threads = 16 warps; warp w owns m-tiles {2w, 2w+1} of G[512, n<=8].
// A register-resident; B = h fp16 in smem; D -> gate smem; fast activations.
#define HB_STRIDE 136   // halves per hb row
#define SG_STRIDE 6     // floats per sgb row (8B-aligned float2 stores)
__global__ __launch_bounds__(512, 1) void k_lstm(int task, float* __restrict__ out_ext) {
    const float* __restrict__ xg = task ? d_xg_t : d_xg_s;
    const uint4* __restrict__ Wf = task ? d_Wft : d_Wfs;
    float* __restrict__ Hout = task ? out_ext : d_Hsh;

    __shared__ __align__(16) __half hb[8 * HB_STRIDE];     // B: [n][k] fp16
    __shared__ __align__(16) float sgb[512 * SG_STRIDE];   // G: [m][n] fp32

    int tid = threadIdx.x;
    int warp = tid >> 5, lane = tid & 31;
    int g = lane >> 2, tg = lane & 3;
    int bc = tid >> 7, uc = tid & 127;   // cell-update assignment (batch, unit)

    uint4 af[16];
    #pragma unroll
    for (int i = 0; i < 16; i++) af[i] = Wf[(warp * 16 + i) * 32 + lane];

    for (int j = tid; j < 8 * HB_STRIDE; j += 512) hb[j] = __float2half(0.0f);
    float c_reg = 0.0f;
    __syncthreads();

    for (int t = 0; t < Tv; t++) {
        // prefetch xg for this thread's cell (hidden under mma phase)
        const float* xr = xg + ((size_t)t * Bv + bc) * Gv + uc;
        float xgi = xr[0], xgf = xr[128], xgg = xr[256], xgo = xr[384];

        // load B fragments from hb
        uint32_t bf0[8], bf1[8];
        #pragma unroll
        for (int kt = 0; kt < 8; kt++) {
            int base = g * HB_STRIDE + kt * 16 + tg * 2;
            bf0[kt] = *reinterpret_cast<const uint32_t*>(&hb[base]);
            bf1[kt] = *reinterpret_cast<const uint32_t*>(&hb[base + 8]);
        }

        // 16 mma: 2 m-tiles x 8 k-tiles, interleaved accumulator chains
        float d0[4] = {0.f, 0.f, 0.f, 0.f};
        float d1[4] = {0.f, 0.f, 0.f, 0.f};
        #pragma unroll
        for (int kt = 0; kt < 8; kt++) {
            mma16816(d0[0], d0[1], d0[2], d0[3], af[kt],     bf0[kt], bf1[kt]);
            mma16816(d1[0], d1[1], d1[2], d1[3], af[8 + kt], bf0[kt], bf1[kt]);
        }

        // store D (only n<4 columns, i.e. tg<2)
        if (tg < 2) {
            int m0 = warp * 32;
            *reinterpret_cast<float2*>(&sgb[(m0 + g)      * SG_STRIDE + tg * 2]) = make_float2(d0[0], d0[1]);
            *reinterpret_cast<float2*>(&sgb[(m0 + g + 8)  * SG_STRIDE + tg * 2]) = make_float2(d0[2], d0[3]);
            *reinterpret_cast<float2*>(&sgb[(m0 + g + 16) * SG_STRIDE + tg * 2]) = make_float2(d1[0], d1[1]);
            *reinterpret_cast<float2*>(&sgb[(m0 + g + 24) * SG_STRIDE + tg * 2]) = make_float2(d1[2], d1[3]);
        }
        __syncthreads();

        // cell update: one (batch, unit) per thread, fast activations
        {
            float gi = sgb[(uc)       * SG_STRIDE + bc] + xgi;
            float gf = sgb[(128 + uc) * SG_STRIDE + bc] + xgf;
            float gg = sgb[(256 + uc) * SG_STRIDE + bc] + xgg;
            float go = sgb[(384 + uc) * SG_STRIDE + bc] + xgo;
            float iv = fsig_fast(gi), fv = fsig_fast(gf), ov = fsig_fast(go);
            float gt = ftanh_fast(gg);
            c_reg = fv * c_reg + iv * gt;
            float hv = ov * ftanh_fast(c_reg);
            hb[bc * HB_STRIDE + uc] = __float2half(hv);
            Hout[((size_t)bc * Tv + t) * Hv + uc] = hv;
        }
        __syncthreads();
    }
}

// ---------------- attention projections (4 rows / block, grid 512) -------
__global__ __launch_bounds__(128) void k_att_proj(
    const float* __restrict__ x,
    const float* __restrict__ Wx, const float* __restrict__ Wht,
    const float* __restrict__ Whs, const float* __restrict__ bs) {
    int b = blockIdx.y;
    int t0 = blockIdx.x * 4;
    __shared__ float sx[4][Iv];
    __shared__ float shh[4][Hv];
    int tid = threadIdx.x;  // 128
    {
        int tt = tid >> 5;
        int k0 = (tid & 31) * 4;
        #pragma unroll
        for (int q = 0; q < 4; q++) {
            sx[tt][k0 + q]  = x[((b * Tv) + (t0 + tt)) * Iv + k0 + q];
            shh[tt][k0 + q] = d_Hsh[((b * Tv) + (t0 + tt)) * Hv + k0 + q];
        }
    }
    __syncthreads();
    int n = tid;
    float at[4], ac[4];
    float bsn = bs[n];
    #pragma unroll
    for (int tt = 0; tt < 4; tt++) { at[tt] = 0.f; ac[tt] = bsn; }
    #pragma unroll 4
    for (int k = 0; k < 128; k++) {
        float wt = Wht[k * Hv + n];
        float ws = Whs[k * Hv + n];
        float wx = Wx [k * Hv + n];
        #pragma unroll
        for (int tt = 0; tt < 4; tt++) {
            at[tt] = fmaf(shh[tt][k], wt, at[tt]);
            ac[tt] = fmaf(sx[tt][k], wx, fmaf(shh[tt][k], ws, ac[tt]));
        }
    }
    #pragma unroll
    for (int tt = 0; tt < 4; tt++) {
        d_hpt[((b * Tv) + (t0 + tt)) * Hv + n] = at[tt];
        d_ca [((b * Tv) + (t0 + tt)) * Hv + n] = ac[tt];
    }
}

// ---------------- attention scores (raw; softmax fused into k_R) ---------
__global__ __launch_bounds__(256) void k_scores(
    const float* __restrict__ u, const float* __restrict__ bu) {
    int b = blockIdx.z;
    int t0 = blockIdx.y * 32;
    int s0 = blockIdx.x * 32;
    __shared__ float sat[32][128];
    __shared__ float scs[32][129];
    __shared__ float su[128];
    int tid = threadIdx.y * 32 + threadIdx.x;  // 256
    for (int i = tid; i < 32 * 128; i += 256) {
        int r = i >> 7, h = i & 127;
        sat[r][h] = d_hpt[((b * Tv) + (t0 + r)) * Hv + h];
        scs[r][h] = d_ca [((b * Tv) + (s0 + r)) * Hv + h];
    }
    if (tid < 128) su[tid] = u[tid];
    __syncthreads();
    int si = threadIdx.x;       // 0..31
    int ti = threadIdx.y * 4;   // 0..28
    float a0 = 0.f, a1 = 0.f, a2 = 0.f, a3 = 0.f;
    #pragma unroll 4
    for (int h = 0; h < 128; h++) {
        float cv = scs[si][h];
        float uv = su[h];
        a0 = fmaf(uv, ftanh_fast(sat[ti + 0][h] + cv), a0);
        a1 = fmaf(uv, ftanh_fast(sat[ti + 1][h] + cv), a1);
        a2 = fmaf(uv, ftanh_fast(sat[ti + 2][h] + cv), a2);
        a3 = fmaf(uv, ftanh_fast(sat[ti + 3][h] + cv), a3);
    }
    float bub = bu[0];
    d_sc[((size_t)(b * Tv) + (t0 + ti + 0)) * Tv + s0 + si] = a0 + bub;
    d_sc[((size_t)(b * Tv) + (t0 + ti + 1)) * Tv + s0 + si] = a1 + bub;
    d_sc[((size_t)(b * Tv) + (t0 + ti + 2)) * Tv + s0 + si] = a2 + bub;
    d_sc[((size_t)(b * Tv) + (t0 + ti + 3)) * Tv + s0 + si] = a3 + bub;
}

// ---------------- fused softmax + R ----------------
// R[b,t,h] = sum_s softmax_s(scores[b,t,:])[s] * Hsh[b,s,h]
__global__ __launch_bounds__(128) void k_R() {
    int b = blockIdx.y;
    int t0 = blockIdx.x * 8;
    __shared__ float sb[8][Tv];
    int tid = threadIdx.x;  // 128
    int warp = tid >> 5, lane = tid & 31;
    for (int i = tid; i < 8 * Tv; i += 128) {
        int tt = i >> 9, s = i & 511;
        sb[tt][s] = d_sc[((size_t)(b * Tv) + (t0 + tt)) * Tv + s];
    }
    __syncthreads();
    // softmax rows: warp w handles rows 2w, 2w+1
    #pragma unroll
    for (int q = 0; q < 2; q++) {
        int r = 2 * warp + q;
        float m = -1e30f;
        #pragma unroll 4
        for (int s = lane; s < Tv; s += 32) m = fmaxf(m, sb[r][s]);
        #pragma unroll
        for (int off = 16; off > 0; off >>= 1)
            m = fmaxf(m, __shfl_xor_sync(0xFFFFFFFF, m, off));
        float sum = 0.f;
        #pragma unroll 4
        for (int s = lane; s < Tv; s += 32) {
            float e = __expf(sb[r][s] - m);
            sb[r][s] = e;
            sum += e;
        }
        #pragma unroll
        for (int off = 16; off > 0; off >>= 1)
            sum += __shfl_xor_sync(0xFFFFFFFF, sum, off);
        float inv = __fdividef(1.0f, sum);
        #pragma unroll 4
        for (int s = lane; s < Tv; s += 32) sb[r][s] *= inv;
    }
    __syncthreads();
    float acc[8];
    #pragma unroll
    for (int tt = 0; tt < 8; tt++) acc[tt] = 0.f;
    int h = tid;
    #pragma unroll 4
    for (int s = 0; s < Tv; s++) {
        float hv = d_Hsh[((b * Tv) + s) * Hv + h];
        #pragma unroll
        for (int tt = 0; tt < 8; tt++) acc[tt] = fmaf(sb[tt][s], hv, acc[tt]);
    }
    #pragma unroll
    for (int tt = 0; tt < 8; tt++)
        d_R[((b * Tv) + (t0 + tt)) * Hv + h] = acc[tt];
}

// ---------------- launch ----------------
extern "C" void kernel_launch(void* const* d_in, const int* in_sizes, int n_in,
                              void* d_out, int out_size) {
    const float* x       = (const float*)d_in[0];
    const float* Wih_s   = (const float*)d_in[1];
    const float* Whh_s   = (const float*)d_in[2];
    const float* b_lstms = (const float*)d_in[3];
    const float* Wx      = (const float*)d_in[4];
    const float* Wht     = (const float*)d_in[5];
    const float* Whs     = (const float*)d_in[6];
    const float* bs      = (const float*)d_in[7];
    const float* u       = (const float*)d_in[8];
    const float* bu      = (const float*)d_in[9];
    const float* Wih_t   = (const float*)d_in[10];
    const float* Whh_t   = (const float*)d_in[11];
    const float* b_lstmt = (const float*)d_in[12];
    float* out = (float*)d_out;

    k_prep<<<256, 256>>>(Wih_s, Wih_t, Whh_s, Whh_t);

    // shared LSTM
    k_proj_gates<<<dim3(Tv / 4, Bv), 512>>>(x, b_lstms, 0);
    k_lstm<<<1, 512>>>(0, out);

    // attention
    k_att_proj<<<dim3(Tv / 4, Bv), 128>>>(x, Wx, Wht, Whs, bs);
    k_scores<<<dim3(Tv / 32, Tv / 32, Bv), dim3(32, 8)>>>(u, bu);
    k_R<<<dim3(Tv / 8, Bv), 128>>>();

    // task LSTM
    k_proj_gates<<<dim3(Tv / 4, Bv), 512>>>(x, b_lstmt, 1);
    k_lstm<<<1, 512>>>(1, out);
}